// round 16
// baseline (speedup 1.0000x reference)
#include <cuda_runtime.h>
#include <cuda_fp16.h>
#include <math.h>
#include <stdint.h>

#define Bb 2
#define LQ 1024
#define LKV 4096
#define Hh 1024
#define HD 64
#define MQ (Bb*LQ)        // 2048
#define MKV (Bb*LKV)      // 8192
#define LN_EPS 1e-12f
#define NEG_INF __int_as_float(0xff800000)

// ---------------- scratch (device globals; no allocation) ----------------
__device__ float g_Q[MQ*Hh];
__device__ float g_V[MQ*Hh*4];            // V fp32 [b][kv][h*64+d]
__device__ float g_ctx[MQ*Hh];
__device__ float g_y[MQ*Hh];
// K fp16 hi, head-major: [bh][kv][64]
__device__ __half g_Kh[(size_t)Bb*16 * LKV * 64];
// V transposed fp16 hi: [bh][d(64)][kv(4096)]
__device__ __half g_Vt[(size_t)Bb*16 * 64 * LKV];

// ================= HMMA fp16 helper =================
__device__ __forceinline__ void mma16816h(float* d, const uint32_t* a,
                                          uint32_t b0, uint32_t b1) {
    asm volatile(
        "mma.sync.aligned.m16n8k16.row.col.f32.f16.f16.f32 "
        "{%0,%1,%2,%3}, {%4,%5,%6,%7}, {%8,%9}, {%0,%1,%2,%3};"
        : "+f"(d[0]), "+f"(d[1]), "+f"(d[2]), "+f"(d[3])
        : "r"(a[0]), "r"(a[1]), "r"(a[2]), "r"(a[3]), "r"(b0), "r"(b1));
}

__device__ __forceinline__ uint32_t pack_h2(float a, float b) {
    __half2 h = __floats2half2_rn(a, b);
    return *(uint32_t*)&h;
}

#define APA 72   // A smem pitch (64 data cols [hi32|lo32] + pad)
#define APB 40   // B smem pitch (32 data cols [hi32] + pad)

// 128x32 fp32 -> [hi32|lo32] fp16 smem (A side)
__device__ __forceinline__ void stage_a32(const float* __restrict__ g, int ldg,
                                          __half* __restrict__ s, int tid)
{
#pragma unroll
    for (int i = 0; i < 4; i++) {
        int idx = tid + i * 256;
        int rr = idx >> 3, c4 = (idx & 7) * 4;
        float4 v = *(const float4*)&g[(size_t)rr * ldg + c4];
        __half h0 = __float2half(v.x), h1 = __float2half(v.y);
        __half h2 = __float2half(v.z), h3 = __float2half(v.w);
        __half2 H01; H01.x = h0; H01.y = h1;
        __half2 H23; H23.x = h2; H23.y = h3;
        __half2 L01, L23;
        L01.x = __float2half(v.x - __half2float(h0));
        L01.y = __float2half(v.y - __half2float(h1));
        L23.x = __float2half(v.z - __half2float(h2));
        L23.y = __float2half(v.w - __half2float(h3));
        __half* o = s + rr * APA + c4;
        *(__half2*)(o)      = H01; *(__half2*)(o + 2)  = H23;
        *(__half2*)(o + 32) = L01; *(__half2*)(o + 34) = L23;
    }
}

// 128x32 fp32 -> [hi32] fp16 smem (B side)
__device__ __forceinline__ void stage_b32(const float* __restrict__ g, int ldg,
                                          __half* __restrict__ s, int tid)
{
#pragma unroll
    for (int i = 0; i < 4; i++) {
        int idx = tid + i * 256;
        int rr = idx >> 3, c4 = (idx & 7) * 4;
        float4 v = *(const float4*)&g[(size_t)rr * ldg + c4];
        __half2 H01; H01.x = __float2half(v.x); H01.y = __float2half(v.y);
        __half2 H23; H23.x = __float2half(v.z); H23.y = __float2half(v.w);
        __half* o = s + rr * APB + c4;
        *(__half2*)(o) = H01; *(__half2*)(o + 2) = H23;
    }
}

// k-loop: 64 A-cols, B reused via kk&31. warp tile 64x32.
__device__ __forceinline__ void mma_chunk64(const __half* As, const __half* Bs,
                                            int wm, int wn, int r, int cq, float acc[4][4][4])
{
#pragma unroll
    for (int kk = 0; kk < 64; kk += 16) {
        uint32_t af[4][4];
#pragma unroll
        for (int mt = 0; mt < 4; mt++) {
            const __half* ab = &As[(wm + mt*16 + r)*APA + kk + cq*2];
            af[mt][0] = *(const uint32_t*)(ab);
            af[mt][1] = *(const uint32_t*)(ab + 8*APA);
            af[mt][2] = *(const uint32_t*)(ab + 8);
            af[mt][3] = *(const uint32_t*)(ab + 8*APA + 8);
        }
#pragma unroll
        for (int nt = 0; nt < 4; nt++) {
            const __half* bb = &Bs[(wn + nt*8 + r)*APB + (kk & 31) + cq*2];
            uint32_t b0 = *(const uint32_t*)(bb);
            uint32_t b1 = *(const uint32_t*)(bb + 8);
#pragma unroll
            for (int mt = 0; mt < 4; mt++)
                mma16816h(acc[mt][nt], af[mt], b0, b1);
        }
    }
}

// ================= projection GEMM =================
// outKh != null: write fp16 head-major [bh][kv][64] (K path); else fp32 out(+bias/res)
__global__ __launch_bounds__(256) void proj_gemm(
    const float* __restrict__ X, const float* __restrict__ W,
    const float* __restrict__ bias, const float* __restrict__ res,
    float* __restrict__ out, __half* __restrict__ outKh)
{
    __shared__ __half As[128*APA];
    __shared__ __half Bs[128*APB];
    __shared__ float stage[128];
    const int tid = threadIdx.x, warp = tid >> 5, lane = tid & 31;
    const int m0 = blockIdx.y * 128, n0 = blockIdx.x * 128;
    const float* Ap = X + (size_t)m0 * Hh;
    const float* Bp = W + (size_t)n0 * Hh;

    if (tid < 128) stage[tid] = bias[n0 + tid];

    const int wm = (warp >> 2) * 64, wn = (warp & 3) * 32;
    const int r = lane >> 2, cq = lane & 3;

    float acc[4][4][4];
#pragma unroll
    for (int mt = 0; mt < 4; mt++)
#pragma unroll
        for (int nt = 0; nt < 4; nt++)
#pragma unroll
            for (int j = 0; j < 4; j++) acc[mt][nt][j] = 0.f;

    for (int c = 0; c < 32; c++) {
        stage_a32(Ap + c*32, Hh, As, tid);
        stage_b32(Bp + c*32, Hh, Bs, tid);
        __syncthreads();
        mma_chunk64(As, Bs, wm, wn, r, cq, acc);
        __syncthreads();
    }

#pragma unroll
    for (int mt = 0; mt < 4; mt++) {
        const int mA = m0 + wm + mt*16 + r;
#pragma unroll
        for (int nt = 0; nt < 4; nt++) {
            const int nl = wn + nt*8 + cq*2;
            const int nA = n0 + nl;
            float bx = stage[nl], by = stage[nl + 1];
            float2 v0, v1;
            v0.x = acc[mt][nt][0] + bx; v0.y = acc[mt][nt][1] + by;
            v1.x = acc[mt][nt][2] + bx; v1.y = acc[mt][nt][3] + by;
            if (outKh) {
                const int h = nA >> 6, d = nA & 63;
                const int bi = mA >> 12, kv = mA & 4095;
                __half* kb = outKh + (((size_t)(bi*16 + h)) * LKV + kv) * 64 + d;
                __half2 h0 = __floats2half2_rn(v0.x, v0.y);
                __half2 h1 = __floats2half2_rn(v1.x, v1.y);
                *(__half2*)(kb)          = h0;
                *(__half2*)(kb + 8 * 64) = h1;
            } else {
                if (res) {
                    float2 r0 = *(const float2*)&res[(size_t)mA * Hh + nA];
                    float2 r1 = *(const float2*)&res[(size_t)(mA+8) * Hh + nA];
                    v0.x += r0.x; v0.y += r0.y; v1.x += r1.x; v1.y += r1.y;
                }
                *(float2*)&out[(size_t)mA * Hh + nA]     = v0;
                *(float2*)&out[(size_t)(mA+8) * Hh + nA] = v1;
            }
        }
    }
}

// ================= V transpose (fp16 hi) -> [bh][d][kv] =================
__global__ __launch_bounds__(256) void splitT_v(const float* __restrict__ V,
                                                __half* __restrict__ vt)
{
    __shared__ float t[64 * 65];
    const int bh = blockIdx.y, c = blockIdx.x;
    const int b = bh >> 4, h = bh & 15;
    const int tid = threadIdx.x;
    const float* src = V + ((size_t)b * LKV + c * 64) * Hh + h * 64;
#pragma unroll
    for (int i = 0; i < 16; i++) {
        int idx = tid + i * 256;
        int kv = idx >> 6, d = idx & 63;
        t[kv * 65 + d] = src[(size_t)kv * Hh + d];
    }
    __syncthreads();
#pragma unroll
    for (int i = 0; i < 2; i++) {
        int idx = tid + i * 256;      // 0..511
        int d = idx >> 3, v8 = (idx & 7) * 8;
        __half hs[8];
#pragma unroll
        for (int j = 0; j < 8; j++)
            hs[j] = __float2half(t[(v8 + j) * 65 + d]);
        *(uint4*)&vt[((size_t)bh * 64 + d) * LKV + c * 64 + v8] = *(uint4*)hs;
    }
}

// ================= fused flash attention (128-q tiles, fp16 K) =================
// grid (LQ/128, 32), block 256 (8 warps; each warp: 16 q rows x full kv tile)
#define QP 136
#define KP 72
#define VP 136
#define FA_SMEM (128*QP*2 + 128*KP*2 + 64*VP*2 + 512)
__global__ __launch_bounds__(256) void flash_attn(
    const float* __restrict__ Qf, const __half* __restrict__ kh,
    const __half* __restrict__ vt, const int* __restrict__ mask,
    float* __restrict__ S)
{
    extern __shared__ char sm8[];
    __half* Qs = (__half*)sm8;
    __half* Ks = Qs + 128*QP;
    __half* Vs = Ks + 128*KP;
    int* maskS = (int*)(Vs + 64*VP);

    const int tid = threadIdx.x, warp = tid >> 5, lane = tid & 31;
    const int q0 = blockIdx.x * 128, bh = blockIdx.y;
    const int b = bh >> 4, h = bh & 15;
    const int r = lane >> 2, cq = lane & 3;
    const int wq = warp * 16;

    // stage Q tile once: 128 rows x 64 fp32 -> [hi64|lo64] fp16
    {
        const float* Ap = Qf + ((size_t)(b*LQ + q0)) * Hh + h*64;
#pragma unroll
        for (int i = 0; i < 8; i++) {
            int idx = tid + i * 256;      // 0..2047
            int rr = idx >> 4, c4 = (idx & 15) * 4;
            float4 v = *(const float4*)&Ap[(size_t)rr * Hh + c4];
            __half h0=__float2half(v.x), h1=__float2half(v.y);
            __half h2=__float2half(v.z), h3=__float2half(v.w);
            __half2 H01; H01.x=h0; H01.y=h1;
            __half2 H23; H23.x=h2; H23.y=h3;
            __half2 L01, L23;
            L01.x=__float2half(v.x-__half2float(h0)); L01.y=__float2half(v.y-__half2float(h1));
            L23.x=__float2half(v.z-__half2float(h2)); L23.y=__float2half(v.w-__half2float(h3));
            __half* o = Qs + rr*QP + c4;
            *(__half2*)o      = H01; *(__half2*)(o+2)  = H23;
            *(__half2*)(o+64) = L01; *(__half2*)(o+66) = L23;
        }
    }

    float cacc[8][4];
#pragma unroll
    for (int nt = 0; nt < 8; nt++)
#pragma unroll
        for (int j = 0; j < 4; j++) cacc[nt][j] = 0.f;
    float mrun0 = NEG_INF, mrun1 = NEG_INF, srun0 = 0.f, srun1 = 0.f;

    const __half* Khb = kh + (size_t)bh * LKV * 64;
    const __half* Vbase = vt + (size_t)bh * 64 * LKV;
    float* Sb = S + ((size_t)bh * LQ + q0) * LKV;

    for (int t = 0; t < 32; t++) {
        const int kv0 = t * 128;
        __syncthreads();   // previous tile's smem reads complete
        // K tile: pure fp16 copy, 128 kv rows x 64 hd
#pragma unroll
        for (int i = 0; i < 4; i++) {
            int idx = tid + i * 256;     // 0..1023
            int rr = idx >> 3, c8 = (idx & 7) * 8;
            *(uint4*)&Ks[rr*KP + c8] = *(const uint4*)&Khb[(size_t)(kv0+rr) * 64 + c8];
        }
        // V tile: 64 d rows x 128 kv fp16
#pragma unroll
        for (int i = 0; i < 4; i++) {
            int idx = tid + i * 256;     // 0..1023
            int d = idx >> 4, v8 = (idx & 15) * 8;
            *(uint4*)&Vs[d*VP + v8] = *(const uint4*)&Vbase[(size_t)d * LKV + kv0 + v8];
        }
        if (tid < 128) maskS[tid] = mask[b*LKV + kv0 + tid];
        __syncthreads();

        // ---- scores: S tile fragments, k' = 128 = [Qhi|Qlo] ----
        float sacc[16][4];
#pragma unroll
        for (int j = 0; j < 16; j++)
#pragma unroll
            for (int k = 0; k < 4; k++) sacc[j][k] = 0.f;
#pragma unroll
        for (int kk = 0; kk < 128; kk += 16) {
            const __half* ab = &Qs[(wq + r)*QP + kk + cq*2];
            uint32_t a[4];
            a[0] = *(const uint32_t*)(ab);
            a[1] = *(const uint32_t*)(ab + 8*QP);
            a[2] = *(const uint32_t*)(ab + 8);
            a[3] = *(const uint32_t*)(ab + 8*QP + 8);
#pragma unroll
            for (int j = 0; j < 16; j++) {
                const __half* bb = &Ks[(j*8 + r)*KP + (kk & 63) + cq*2];
                uint32_t b0 = *(const uint32_t*)(bb);
                uint32_t b1 = *(const uint32_t*)(bb + 8);
                mma16816h(sacc[j], a, b0, b1);
            }
        }

        // ---- mask + scale, write S ----
#pragma unroll
        for (int j = 0; j < 16; j++) {
            int c0i = j*8 + cq*2;
            int mx = maskS[c0i], my = maskS[c0i + 1];
            sacc[j][0] = mx ? sacc[j][0]*0.125f : NEG_INF;
            sacc[j][1] = my ? sacc[j][1]*0.125f : NEG_INF;
            sacc[j][2] = mx ? sacc[j][2]*0.125f : NEG_INF;
            sacc[j][3] = my ? sacc[j][3]*0.125f : NEG_INF;
            int cc = kv0 + c0i;
            *(float2*)&Sb[(size_t)(wq + r)     * LKV + cc] = make_float2(sacc[j][0], sacc[j][1]);
            *(float2*)&Sb[(size_t)(wq + r + 8) * LKV + cc] = make_float2(sacc[j][2], sacc[j][3]);
        }

        // ---- online softmax ----
        float mt0 = NEG_INF, mt1 = NEG_INF;
#pragma unroll
        for (int j = 0; j < 16; j++) {
            mt0 = fmaxf(mt0, fmaxf(sacc[j][0], sacc[j][1]));
            mt1 = fmaxf(mt1, fmaxf(sacc[j][2], sacc[j][3]));
        }
        mt0 = fmaxf(mt0, __shfl_xor_sync(0xFFFFFFFF, mt0, 1));
        mt0 = fmaxf(mt0, __shfl_xor_sync(0xFFFFFFFF, mt0, 2));
        mt1 = fmaxf(mt1, __shfl_xor_sync(0xFFFFFFFF, mt1, 1));
        mt1 = fmaxf(mt1, __shfl_xor_sync(0xFFFFFFFF, mt1, 2));
        float mn0 = fmaxf(mrun0, mt0), mn1 = fmaxf(mrun1, mt1);
        float al0 = (mrun0 == NEG_INF) ? 0.f : __expf(mrun0 - mn0);
        float al1 = (mrun1 == NEG_INF) ? 0.f : __expf(mrun1 - mn1);
#pragma unroll
        for (int nt = 0; nt < 8; nt++) {
            cacc[nt][0] *= al0; cacc[nt][1] *= al0;
            cacc[nt][2] *= al1; cacc[nt][3] *= al1;
        }
        float rs0 = 0.f, rs1 = 0.f;
#pragma unroll
        for (int j = 0; j < 16; j++) {
            float p0 = (sacc[j][0] == NEG_INF) ? 0.f : __expf(sacc[j][0] - mn0);
            float p1 = (sacc[j][1] == NEG_INF) ? 0.f : __expf(sacc[j][1] - mn0);
            float p2 = (sacc[j][2] == NEG_INF) ? 0.f : __expf(sacc[j][2] - mn1);
            float p3 = (sacc[j][3] == NEG_INF) ? 0.f : __expf(sacc[j][3] - mn1);
            sacc[j][0] = p0; sacc[j][1] = p1; sacc[j][2] = p2; sacc[j][3] = p3;
            rs0 += p0 + p1; rs1 += p2 + p3;
        }
        rs0 += __shfl_xor_sync(0xFFFFFFFF, rs0, 1);
        rs0 += __shfl_xor_sync(0xFFFFFFFF, rs0, 2);
        rs1 += __shfl_xor_sync(0xFFFFFFFF, rs1, 1);
        rs1 += __shfl_xor_sync(0xFFFFFFFF, rs1, 2);
        srun0 = srun0 * al0 + rs0;
        srun1 = srun1 * al1 + rs1;
        mrun0 = mn0; mrun1 = mn1;

        // ---- P @ V: P fragments from sacc (C->A register pairing) ----
#pragma unroll
        for (int tt = 0; tt < 8; tt++) {
            uint32_t a[4];
            a[0] = pack_h2(sacc[2*tt][0],   sacc[2*tt][1]);
            a[1] = pack_h2(sacc[2*tt][2],   sacc[2*tt][3]);
            a[2] = pack_h2(sacc[2*tt+1][0], sacc[2*tt+1][1]);
            a[3] = pack_h2(sacc[2*tt+1][2], sacc[2*tt+1][3]);
#pragma unroll
            for (int nt = 0; nt < 8; nt++) {
                const __half* bb = &Vs[(nt*8 + r)*VP + tt*16 + cq*2];
                uint32_t b0 = *(const uint32_t*)(bb);
                uint32_t b1 = *(const uint32_t*)(bb + 8);
                mma16816h(cacc[nt], a, b0, b1);
            }
        }
    }

    // ---- epilogue: ctx = cacc / sum ----
    float inv0 = 1.f / srun0, inv1 = 1.f / srun1;
    const int q = q0 + wq + r;
#pragma unroll
    for (int nt = 0; nt < 8; nt++) {
        int d = nt*8 + cq*2;
        *(float2*)&g_ctx[((size_t)(b*LQ + q))     * Hh + h*64 + d] =
            make_float2(cacc[nt][0]*inv0, cacc[nt][1]*inv0);
        *(float2*)&g_ctx[((size_t)(b*LQ + q + 8)) * Hh + h*64 + d] =
            make_float2(cacc[nt][2]*inv1, cacc[nt][3]*inv1);
    }
}

// ---------------- layernorm over last dim ----------------
__global__ __launch_bounds__(256) void ln_kernel(
    const float* __restrict__ Y, const float* __restrict__ w,
    const float* __restrict__ bta, float* __restrict__ out)
{
    const int row = blockIdx.x;
    __shared__ float buf[Hh];
    __shared__ float red[256];
    const int tid = threadIdx.x;
    const float* y = Y + (size_t)row * Hh;

    float s = 0.f;
    for (int i = tid; i < Hh; i += 256) { float v = y[i]; buf[i] = v; s += v; }
    red[tid] = s; __syncthreads();
    for (int st = 128; st > 0; st >>= 1) {
        if (tid < st) red[tid] += red[tid + st];
        __syncthreads();
    }
    const float mu = red[0] * (1.0f / Hh); __syncthreads();

    float vs = 0.f;
    for (int i = tid; i < Hh; i += 256) { float dd = buf[i] - mu; vs += dd * dd; }
    red[tid] = vs; __syncthreads();
    for (int st = 128; st > 0; st >>= 1) {
        if (tid < st) red[tid] += red[tid + st];
        __syncthreads();
    }
    const float inv = rsqrtf(red[0] * (1.0f / Hh) + LN_EPS);

    for (int i = tid; i < Hh; i += 256)
        out[(size_t)row * Hh + i] = (buf[i] - mu) * inv * w[i] + bta[i];
}

// ---------------- launch ----------------
extern "C" void kernel_launch(void* const* d_in, const int* in_sizes, int n_in,
                              void* d_out, int out_size)
{
    (void)in_sizes; (void)n_in; (void)out_size;
    const float* hs   = (const float*)d_in[0];
    const float* ehs  = (const float*)d_in[1];
    const int*   mask = (const int*)  d_in[2];
    const float* q_w  = (const float*)d_in[3];
    const float* q_b  = (const float*)d_in[4];
    const float* k_w  = (const float*)d_in[5];
    const float* k_b  = (const float*)d_in[6];
    const float* v_w  = (const float*)d_in[7];
    const float* v_b  = (const float*)d_in[8];
    const float* o_w  = (const float*)d_in[9];
    const float* o_b  = (const float*)d_in[10];
    const float* ln_w = (const float*)d_in[11];
    const float* ln_b = (const float*)d_in[12];

    float* out  = (float*)d_out;
    float* Sout = out + (size_t)MQ * Hh;

    float *pQ, *pV, *pCtx, *pY;
    cudaGetSymbolAddress((void**)&pQ,   g_Q);
    cudaGetSymbolAddress((void**)&pV,   g_V);
    cudaGetSymbolAddress((void**)&pCtx, g_ctx);
    cudaGetSymbolAddress((void**)&pY,   g_y);
    __half *pKh, *pVt;
    cudaGetSymbolAddress((void**)&pKh, g_Kh);
    cudaGetSymbolAddress((void**)&pVt, g_Vt);

    cudaFuncSetAttribute(flash_attn, cudaFuncAttributeMaxDynamicSharedMemorySize, FA_SMEM);

    // 1) projections (fp16 2-term HMMA). K writes fp16 head-major directly.
    proj_gemm<<<dim3(8, MQ/128),  256>>>(hs,  q_w, q_b, nullptr, pQ, nullptr);
    proj_gemm<<<dim3(8, MKV/128), 256>>>(ehs, k_w, k_b, nullptr, nullptr, pKh);
    proj_gemm<<<dim3(8, MKV/128), 256>>>(ehs, v_w, v_b, nullptr, pV, nullptr);

    // 2) V transpose (fp16, [bh][d][kv])
    splitT_v<<<dim3(64, Bb*16), 256>>>(pV, pVt);

    // 3) fused: masked scores -> S output + online softmax + P@V -> ctx
    flash_attn<<<dim3(LQ/128, Bb*16), 256, FA_SMEM>>>(pQ, pKh, pVt, mask, Sout);

    // 4) O-projection + residual
    proj_gemm<<<dim3(8, MQ/128), 256>>>(pCtx, o_w, o_b, hs, pY, nullptr);

    // 5) layernorm -> first output
    ln_kernel<<<MQ, 256>>>(pY, ln_w, ln_b, out);
}